// round 4
// baseline (speedup 1.0000x reference)
#include <cuda_runtime.h>
#include <cuda_bf16.h>
#include <math.h>
#include <stdint.h>

#define N_NODES 32767
#define HDIM 256
#define H2 512
#define G4 2048
#define VOCAB 32

// ---------------- device state / tables ----------------
__device__ float         g_C[(N_NODES + 1) * HDIM];    // c state, first 256 lanes (sentinel row stays 0)
__device__ __nv_bfloat16 g_Hhi[(N_NODES + 1) * HDIM];  // h hi
__device__ __nv_bfloat16 g_Hlo[(N_NODES + 1) * HDIM];  // h lo
__device__ float         g_xtab[VOCAB * G4];           // unpermuted (small fp32 path)
__device__ float         g_xtabp[VOCAB * G4];          // permuted jj = hid*4+g (tensor path)
__device__ float         g_WhhT[H2 * G4];              // fp32 [k][j] (small path)
__device__ __nv_bfloat16 g_Whi[G4 * H2];               // permuted rows [jj][k] bf16 hi
__device__ __nv_bfloat16 g_Wlo[G4 * H2];               // permuted rows [jj][k] bf16 lo
__device__ float         g_gates[64 * G4];             // small-level gate scratch

__device__ __forceinline__ float sigm(float x) { return 1.0f / (1.0f + expf(-x)); }

__device__ __forceinline__ uint32_t smem_u32(const void* p) {
    uint32_t a;
    asm("{ .reg .u64 t; cvta.to.shared.u64 t, %1; cvt.u32.u64 %0, t; }" : "=r"(a) : "l"(p));
    return a;
}
__device__ __forceinline__ void cpa16(uint32_t dst, const void* src) {
    asm volatile("cp.async.cg.shared.global [%0], [%1], 16;" :: "r"(dst), "l"(src));
}
__device__ __forceinline__ void cp_commit() { asm volatile("cp.async.commit_group;"); }
__device__ __forceinline__ void cp_wait1() { asm volatile("cp.async.wait_group 1;"); }
__device__ __forceinline__ void cp_wait0() { asm volatile("cp.async.wait_group 0;"); }

__device__ __forceinline__ void ldmatrix4(uint32_t& r0, uint32_t& r1, uint32_t& r2, uint32_t& r3,
                                          uint32_t addr) {
    asm volatile("ldmatrix.sync.aligned.m8n8.x4.shared.b16 {%0,%1,%2,%3}, [%4];"
                 : "=r"(r0), "=r"(r1), "=r"(r2), "=r"(r3) : "r"(addr));
}
__device__ __forceinline__ void mma16816(float& d0, float& d1, float& d2, float& d3,
                                         uint32_t a0, uint32_t a1, uint32_t a2, uint32_t a3,
                                         uint32_t b0, uint32_t b1) {
    asm volatile(
        "mma.sync.aligned.m16n8k16.row.col.f32.bf16.bf16.f32 "
        "{%0,%1,%2,%3}, {%4,%5,%6,%7}, {%8,%9}, {%0,%1,%2,%3};"
        : "+f"(d0), "+f"(d1), "+f"(d2), "+f"(d3)
        : "r"(a0), "r"(a1), "r"(a2), "r"(a3), "r"(b0), "r"(b1));
}

#define SWZ(x) ((x) ^ (((x) >> 3) & 0x70))

// ---------------- smem layout (dynamic) ----------------
// meta: sa[128] sb[128] sty[128]
#define OFF_META   0
#define OFF_STAGE  2048
#define A_BYTES    16384            // 128 rows x 128B (SW128)
#define B_STRIDE   144              // 72 bf16 per row (64 data + 8 pad)
#define B_BYTES    (128 * B_STRIDE) // 18432
#define STAGE_SZ   (2 * A_BYTES + 2 * B_BYTES)   // Ahi, Alo, Bhi, Blo = 69632
#define ST_AHI     0
#define ST_ALO     A_BYTES
#define ST_BHI     (2 * A_BYTES)
#define ST_BLO     (2 * A_BYTES + B_BYTES)
#define SMEM_DYN   (OFF_STAGE + 2 * STAGE_SZ)    // 141312
#define GST        132              // gate staging row stride (floats)

// ---------------- prep kernels ----------------
__global__ __launch_bounds__(256) void xtab_kernel(const float* __restrict__ emb,
                                                   const float* __restrict__ W_ih,
                                                   const float* __restrict__ b_ih,
                                                   const float* __restrict__ b_hh) {
    __shared__ float se[256];
    int v = blockIdx.x;
    int t = threadIdx.x;
    se[t] = emb[v * 256 + t];
    __syncthreads();
    #pragma unroll
    for (int m = 0; m < 8; m++) {
        int j = m * 256 + t;
        float acc = b_ih[j] + b_hh[j];
        const float4* wr = (const float4*)(W_ih + j * 256);
        #pragma unroll 8
        for (int k4 = 0; k4 < 64; k4++) {
            float4 w = wr[k4];
            acc += w.x * se[k4 * 4 + 0] + w.y * se[k4 * 4 + 1]
                 + w.z * se[k4 * 4 + 2] + w.w * se[k4 * 4 + 3];
        }
        g_xtab[v * G4 + j] = acc;
        g_xtabp[v * G4 + (j & 511) * 4 + (j >> 9)] = acc;
    }
}

__global__ void transpose_kernel(const float* __restrict__ W_hh) {
    __shared__ float tile[32][33];
    int j0 = blockIdx.x * 32;
    int k0 = blockIdx.y * 32;
    int tx = threadIdx.x, ty = threadIdx.y;
    #pragma unroll
    for (int r = 0; r < 32; r += 8)
        tile[ty + r][tx] = W_hh[(j0 + ty + r) * H2 + k0 + tx];
    __syncthreads();
    #pragma unroll
    for (int r = 0; r < 32; r += 8)
        g_WhhT[(k0 + ty + r) * G4 + j0 + tx] = tile[tx][ty + r];
}

__global__ __launch_bounds__(256) void wconv_kernel(const float* __restrict__ W_hh) {
    int jj = blockIdx.x;
    int g = jj & 3, hid = jj >> 2;
    const float* src = W_hh + (g * 512 + hid) * H2;
    int t = threadIdx.x;
    #pragma unroll
    for (int k = t; k < H2; k += 256) {
        float w = src[k];
        __nv_bfloat16 hi = __float2bfloat16(w);
        __nv_bfloat16 lo = __float2bfloat16(w - __bfloat162float(hi));
        g_Whi[jj * H2 + k] = hi;
        g_Wlo[jj * H2 + k] = lo;
    }
}

// ---------------- HMMA level kernel: M=128 nodes, N=128 gates (by slice), K=512 ----------------
__global__ __launch_bounds__(256) void tc_level_kernel(
    const int* __restrict__ types, const int* __restrict__ a_idx,
    const int* __restrict__ b_idx, float* __restrict__ out, int s) {
    extern __shared__ char sp[];
    uint32_t sbase = smem_u32(sp);
    int tid = threadIdx.x;
    int lane = tid & 31;
    int wid = tid >> 5;
    int wm = wid >> 2;            // 0..1  (M half)
    int wn = wid & 3;             // 0..3  (N quarter)
    int by = blockIdx.y;          // gate slice jj in [by*128, by*128+128)
    int base = s + blockIdx.x * 128;

    int* sa  = (int*)(sp + OFF_META);
    int* sbb = (int*)(sp + OFF_META + 512);
    int* sty = (int*)(sp + OFF_META + 1024);
    if (tid < 128) {
        int i = base + tid;
        sa[tid]  = a_idx[i];
        sbb[tid] = b_idx[i];
        sty[tid] = types[i];
    }
    __syncthreads();

    int arow = tid >> 1, ahalf = tid & 1;   // A/B loaders: 2 threads per row

    // ---- chunk loader (Kc = 64) ----
    auto load_chunk = [&](int kc, int st) {
        uint32_t stg = sbase + OFF_STAGE + st * STAGE_SZ;
        // A: 128 rows x 128B, SW128 swizzle
        int child = (kc < 4) ? sa[arow] : sbb[arow];
        int col0 = (kc & 3) * 64 + ahalf * 32;
        const char* ah = (const char*)(g_Hhi + (size_t)child * HDIM + col0);
        const char* al = (const char*)(g_Hlo + (size_t)child * HDIM + col0);
        #pragma unroll
        for (int q = 0; q < 4; q++) {
            uint32_t boff = arow * 128 + ahalf * 64 + q * 16;
            cpa16(stg + ST_AHI + SWZ(boff), ah + q * 16);
            cpa16(stg + ST_ALO + SWZ(boff), al + q * 16);
        }
        // B: 128 rows (jj) x 128B data, padded stride 144B
        const char* wh = (const char*)(g_Whi + (size_t)(by * 128 + arow) * H2 + kc * 64 + ahalf * 32);
        const char* wl = (const char*)(g_Wlo + (size_t)(by * 128 + arow) * H2 + kc * 64 + ahalf * 32);
        #pragma unroll
        for (int q = 0; q < 4; q++) {
            uint32_t boff = arow * B_STRIDE + ahalf * 64 + q * 16;
            cpa16(stg + ST_BHI + boff, wh + q * 16);
            cpa16(stg + ST_BLO + boff, wl + q * 16);
        }
        cp_commit();
    };

    float acc[4][4][4];
    #pragma unroll
    for (int mt = 0; mt < 4; mt++)
        #pragma unroll
        for (int nb = 0; nb < 4; nb++)
            #pragma unroll
            for (int r = 0; r < 4; r++) acc[mt][nb][r] = 0.0f;

    load_chunk(0, 0);

    for (int kc = 0; kc < 8; kc++) {
        if (kc < 7) load_chunk(kc + 1, (kc + 1) & 1);
        if (kc < 7) cp_wait1(); else cp_wait0();
        __syncthreads();

        uint32_t stg = sbase + OFF_STAGE + (kc & 1) * STAGE_SZ;
        const char* bhiP = sp + (OFF_STAGE + (kc & 1) * STAGE_SZ + ST_BHI);
        const char* bloP = sp + (OFF_STAGE + (kc & 1) * STAGE_SZ + ST_BLO);

        #pragma unroll
        for (int ks = 0; ks < 4; ks++) {
            int k0 = ks * 16;
            // B fragments: n = wn*32 + nb*8 + lane/4 ; k = k0 + j*8 + (lane%4)*2
            uint32_t bhi[4][2], blo[4][2];
            #pragma unroll
            for (int nb = 0; nb < 4; nb++) {
                int n = wn * 32 + nb * 8 + (lane >> 2);
                int kk = k0 + ((lane & 3) << 1);
                bhi[nb][0] = *(const uint32_t*)(bhiP + n * B_STRIDE + kk * 2);
                bhi[nb][1] = *(const uint32_t*)(bhiP + n * B_STRIDE + (kk + 8) * 2);
                blo[nb][0] = *(const uint32_t*)(bloP + n * B_STRIDE + kk * 2);
                blo[nb][1] = *(const uint32_t*)(bloP + n * B_STRIDE + (kk + 8) * 2);
            }
            #pragma unroll
            for (int mt = 0; mt < 4; mt++) {
                int row = wm * 64 + mt * 16 + (lane & 15);
                uint32_t boff = SWZ((uint32_t)(row * 128 + k0 * 2 + (lane >> 4) * 16));
                uint32_t ah0, ah1, ah2, ah3, al0, al1, al2, al3;
                ldmatrix4(ah0, ah1, ah2, ah3, stg + ST_AHI + boff);
                ldmatrix4(al0, al1, al2, al3, stg + ST_ALO + boff);
                #pragma unroll
                for (int nb = 0; nb < 4; nb++) {
                    mma16816(acc[mt][nb][0], acc[mt][nb][1], acc[mt][nb][2], acc[mt][nb][3],
                             ah0, ah1, ah2, ah3, bhi[nb][0], bhi[nb][1]);
                    mma16816(acc[mt][nb][0], acc[mt][nb][1], acc[mt][nb][2], acc[mt][nb][3],
                             ah0, ah1, ah2, ah3, blo[nb][0], blo[nb][1]);
                    mma16816(acc[mt][nb][0], acc[mt][nb][1], acc[mt][nb][2], acc[mt][nb][3],
                             al0, al1, al2, al3, bhi[nb][0], bhi[nb][1]);
                }
            }
        }
        __syncthreads();
    }

    // ---- stage gates to smem (reuse pipeline buffers): [128][GST] floats ----
    float* gates = (float*)(sp + OFF_STAGE);
    #pragma unroll
    for (int mt = 0; mt < 4; mt++) {
        #pragma unroll
        for (int nb = 0; nb < 4; nb++) {
            int r0 = wm * 64 + mt * 16 + (lane >> 2);
            int c0 = wn * 32 + nb * 8 + ((lane & 3) << 1);
            gates[r0 * GST + c0]       = acc[mt][nb][0];
            gates[r0 * GST + c0 + 1]   = acc[mt][nb][1];
            gates[(r0 + 8) * GST + c0]     = acc[mt][nb][2];
            gates[(r0 + 8) * GST + c0 + 1] = acc[mt][nb][3];
        }
    }
    __syncthreads();

    // ---- fused LSTM epilogue: 128 nodes x 32 hids (this by slice) ----
    int hl = tid & 31;                       // hid local 0..31
    int hid_g = by * 32 + hl;
    #pragma unroll 4
    for (int it = 0; it < 16; it++) {
        int m = (tid >> 5) + (it << 3);      // node local 0..127
        int node = base + m;
        int child = (by < 8) ? sa[m] : sbb[m];
        float4 gt = *(const float4*)(gates + m * GST + hl * 4);
        float4 xt = *(const float4*)(g_xtabp + (size_t)sty[m] * G4 + by * 128 + hl * 4);
        float ig = gt.x + xt.x;
        float fg = gt.y + xt.y;
        float gg = gt.z + xt.z;
        float og = gt.w + xt.w;
        float co = g_C[(size_t)child * HDIM + (hid_g & 255)];
        float cn = sigm(fg) * co + sigm(ig) * tanhf(gg);
        float hn = sigm(og) * tanhf(cn);
        out[(size_t)node * H2 + hid_g] = hn;
        if (by < 8) {
            g_C[(size_t)node * HDIM + hid_g] = cn;
            __nv_bfloat16 hi = __float2bfloat16(hn);
            g_Hhi[(size_t)node * HDIM + hid_g] = hi;
            g_Hlo[(size_t)node * HDIM + hid_g] = __float2bfloat16(hn - __bfloat162float(hi));
        }
    }
}

// ---------------- small levels (n <= 64): fp32 path ----------------
__global__ __launch_bounds__(256) void small_gates_kernel(
    const int* __restrict__ types, const int* __restrict__ a_idx,
    const int* __restrict__ b_idx, int s, int n) {
    __shared__ float hbuf[4][H2];
    __shared__ int stype[4], svalid[4], sa4[4], sb4[4];
    int t = threadIdx.x;
    int base = s + blockIdx.x * 4;
    if (t < 4) {
        int i = base + t;
        int v = (i < s + n);
        svalid[t] = v;
        sa4[t] = v ? a_idx[i] : N_NODES;
        sb4[t] = v ? b_idx[i] : N_NODES;
        stype[t] = v ? types[i] : 0;
    }
    __syncthreads();
    #pragma unroll
    for (int it = 0; it < 8; it++) {
        int idx = it * 256 + t;
        int r = idx >> 9;
        int k = idx & 511;
        int child = (k < HDIM) ? sa4[r] : sb4[r];
        int kk = k & 255;
        hbuf[r][k] = __bfloat162float(g_Hhi[child * HDIM + kk])
                   + __bfloat162float(g_Hlo[child * HDIM + kk]);
    }
    __syncthreads();
    int j = blockIdx.y * 256 + t;
    float acc[4];
    #pragma unroll
    for (int r = 0; r < 4; r++) acc[r] = g_xtab[stype[r] * G4 + j];
    #pragma unroll 4
    for (int k = 0; k < H2; k++) {
        float w = g_WhhT[k * G4 + j];
        #pragma unroll
        for (int r = 0; r < 4; r++) acc[r] = fmaf(w, hbuf[r][k], acc[r]);
    }
    #pragma unroll
    for (int r = 0; r < 4; r++)
        if (svalid[r]) g_gates[(blockIdx.x * 4 + r) * G4 + j] = acc[r];
}

__global__ __launch_bounds__(256) void small_epi_kernel(
    const int* __restrict__ a_idx, const int* __restrict__ b_idx,
    float* __restrict__ out, int s) {
    int i = s + blockIdx.x;
    int t = threadIdx.x;
    int a = a_idx[i], b = b_idx[i];
    const float* gr = g_gates + (size_t)blockIdx.x * G4;
    #pragma unroll
    for (int h = 0; h < 2; h++) {
        int hid = (h << 8) + t;
        float ig = gr[0 * 512 + hid];
        float fg = gr[1 * 512 + hid];
        float gg = gr[2 * 512 + hid];
        float og = gr[3 * 512 + hid];
        int child = h ? b : a;
        float c_old = g_C[child * HDIM + t];
        float c_new = sigm(fg) * c_old + sigm(ig) * tanhf(gg);
        float h_new = sigm(og) * tanhf(c_new);
        out[i * H2 + hid] = h_new;
        if (h == 0) {
            g_C[i * HDIM + t] = c_new;
            __nv_bfloat16 hi = __float2bfloat16(h_new);
            g_Hhi[i * HDIM + t] = hi;
            g_Hlo[i * HDIM + t] = __float2bfloat16(h_new - __bfloat162float(hi));
        }
    }
}

extern "C" void kernel_launch(void* const* d_in, const int* in_sizes, int n_in,
                              void* d_out, int out_size) {
    const int* types  = (const int*)d_in[0];
    const int* a_idx  = (const int*)d_in[1];
    const int* b_idx  = (const int*)d_in[2];
    const float* emb  = (const float*)d_in[3];
    const float* W_ih = (const float*)d_in[4];
    const float* W_hh = (const float*)d_in[5];
    const float* b_ih = (const float*)d_in[6];
    const float* b_hh = (const float*)d_in[7];
    float* out = (float*)d_out;

    cudaFuncSetAttribute(tc_level_kernel, cudaFuncAttributeMaxDynamicSharedMemorySize, SMEM_DYN);

    xtab_kernel<<<VOCAB, 256>>>(emb, W_ih, b_ih, b_hh);
    transpose_kernel<<<dim3(G4 / 32, H2 / 32), dim3(32, 8)>>>(W_hh);
    wconv_kernel<<<G4, 256>>>(W_hh);

    for (int d = 14; d >= 7; d--) {
        int n = 1 << d;
        int s = n - 1;
        tc_level_kernel<<<dim3(n / 128, 16), 256, SMEM_DYN>>>(types, a_idx, b_idx, out, s);
    }
    for (int d = 6; d >= 0; d--) {
        int n = 1 << d;
        int s = n - 1;
        small_gates_kernel<<<dim3((n + 3) / 4, 8), 256>>>(types, a_idx, b_idx, s, n);
        small_epi_kernel<<<n, 256>>>(a_idx, b_idx, out, s);
    }
}

// round 5
// speedup vs baseline: 1.1310x; 1.1310x over previous
#include <cuda_runtime.h>
#include <cuda_fp16.h>
#include <math.h>
#include <stdint.h>

#define N_NODES 32767
#define HDIM 256
#define H2 512
#define G4 2048
#define VOCAB 32

// ---------------- device state / tables ----------------
__device__ float  g_C[(N_NODES + 1) * HDIM];    // c state (sentinel row stays 0)
__device__ __half g_Hh[(N_NODES + 1) * HDIM];   // h state fp16 (sentinel row stays 0)
__device__ float  g_xtab[VOCAB * G4];           // unpermuted (small fp32 path)
__device__ float  g_xtabp[VOCAB * G4];          // permuted jj = hid*4+g (tensor path)
__device__ float  g_WhhT[H2 * G4];              // fp32 [k][j] (small path)
__device__ __half g_Wh[G4 * H2];                // permuted rows [jj][k] fp16
__device__ float  g_gates[64 * G4];             // small-level gate scratch

__device__ __forceinline__ float sigm(float x) { return 1.0f / (1.0f + expf(-x)); }

__device__ __forceinline__ uint32_t smem_u32(const void* p) {
    uint32_t a;
    asm("{ .reg .u64 t; cvta.to.shared.u64 t, %1; cvt.u32.u64 %0, t; }" : "=r"(a) : "l"(p));
    return a;
}
__device__ __forceinline__ void cpa16(uint32_t dst, const void* src) {
    asm volatile("cp.async.cg.shared.global [%0], [%1], 16;" :: "r"(dst), "l"(src));
}
__device__ __forceinline__ void cp_commit() { asm volatile("cp.async.commit_group;"); }
__device__ __forceinline__ void cp_wait1() { asm volatile("cp.async.wait_group 1;"); }
__device__ __forceinline__ void cp_wait0() { asm volatile("cp.async.wait_group 0;"); }

__device__ __forceinline__ void ldmatrix4(uint32_t& r0, uint32_t& r1, uint32_t& r2, uint32_t& r3,
                                          uint32_t addr) {
    asm volatile("ldmatrix.sync.aligned.m8n8.x4.shared.b16 {%0,%1,%2,%3}, [%4];"
                 : "=r"(r0), "=r"(r1), "=r"(r2), "=r"(r3) : "r"(addr));
}
__device__ __forceinline__ void mma16816(float& d0, float& d1, float& d2, float& d3,
                                         uint32_t a0, uint32_t a1, uint32_t a2, uint32_t a3,
                                         uint32_t b0, uint32_t b1) {
    asm volatile(
        "mma.sync.aligned.m16n8k16.row.col.f32.f16.f16.f32 "
        "{%0,%1,%2,%3}, {%4,%5,%6,%7}, {%8,%9}, {%0,%1,%2,%3};"
        : "+f"(d0), "+f"(d1), "+f"(d2), "+f"(d3)
        : "r"(a0), "r"(a1), "r"(a2), "r"(a3), "r"(b0), "r"(b1));
}

#define SWZ(x) ((x) ^ (((x) >> 3) & 0x70))

// ---------------- smem layout (dynamic) ----------------
#define OFF_META   0
#define OFF_STAGE  2048
#define A_BYTES    16384            // 128 rows x 128B (SW128), Kc=64 fp16
#define B_STRIDE   144              // 72 fp16 per row (64 data + 8 pad), mult of 16
#define B_BYTES    (128 * B_STRIDE) // 18432
#define STAGE_SZ   (A_BYTES + B_BYTES)   // 34816
#define ST_A       0
#define ST_B       A_BYTES
#define SMEM_DYN   (OFF_STAGE + 2 * STAGE_SZ)    // 71680  -> 2 CTAs/SM
#define GST        132              // gate staging row stride (floats)

// ---------------- prep kernels ----------------
__global__ __launch_bounds__(256) void xtab_kernel(const float* __restrict__ emb,
                                                   const float* __restrict__ W_ih,
                                                   const float* __restrict__ b_ih,
                                                   const float* __restrict__ b_hh) {
    __shared__ float se[256];
    int v = blockIdx.x;
    int t = threadIdx.x;
    se[t] = emb[v * 256 + t];
    __syncthreads();
    #pragma unroll
    for (int m = 0; m < 8; m++) {
        int j = m * 256 + t;
        float acc = b_ih[j] + b_hh[j];
        const float4* wr = (const float4*)(W_ih + j * 256);
        #pragma unroll 8
        for (int k4 = 0; k4 < 64; k4++) {
            float4 w = wr[k4];
            acc += w.x * se[k4 * 4 + 0] + w.y * se[k4 * 4 + 1]
                 + w.z * se[k4 * 4 + 2] + w.w * se[k4 * 4 + 3];
        }
        g_xtab[v * G4 + j] = acc;
        g_xtabp[v * G4 + (j & 511) * 4 + (j >> 9)] = acc;
    }
}

__global__ void transpose_kernel(const float* __restrict__ W_hh) {
    __shared__ float tile[32][33];
    int j0 = blockIdx.x * 32;
    int k0 = blockIdx.y * 32;
    int tx = threadIdx.x, ty = threadIdx.y;
    #pragma unroll
    for (int r = 0; r < 32; r += 8)
        tile[ty + r][tx] = W_hh[(j0 + ty + r) * H2 + k0 + tx];
    __syncthreads();
    #pragma unroll
    for (int r = 0; r < 32; r += 8)
        g_WhhT[(k0 + ty + r) * G4 + j0 + tx] = tile[tx][ty + r];
}

__global__ __launch_bounds__(256) void wconv_kernel(const float* __restrict__ W_hh) {
    int jj = blockIdx.x;
    int g = jj & 3, hid = jj >> 2;
    const float* src = W_hh + (g * 512 + hid) * H2;
    int t = threadIdx.x;
    #pragma unroll
    for (int k = t; k < H2; k += 256)
        g_Wh[jj * H2 + k] = __float2half_rn(src[k]);
}

// ---------------- HMMA level kernel: M=128 nodes, N=128 gates (by slice), K=512 ----------------
__global__ __launch_bounds__(256) void tc_level_kernel(
    const int* __restrict__ types, const int* __restrict__ a_idx,
    const int* __restrict__ b_idx, float* __restrict__ out, int s) {
    extern __shared__ char sp[];
    uint32_t sbase = smem_u32(sp);
    int tid = threadIdx.x;
    int lane = tid & 31;
    int wid = tid >> 5;
    int wm = wid >> 2;            // 0..1  (M half, 64 rows)
    int wn = wid & 3;             // 0..3  (N quarter, 32 cols)
    int by = blockIdx.y;          // gate slice jj in [by*128, by*128+128)
    int base = s + blockIdx.x * 128;

    int* sa  = (int*)(sp + OFF_META);
    int* sbb = (int*)(sp + OFF_META + 512);
    int* sty = (int*)(sp + OFF_META + 1024);
    if (tid < 128) {
        int i = base + tid;
        sa[tid]  = a_idx[i];
        sbb[tid] = b_idx[i];
        sty[tid] = types[i];
    }
    __syncthreads();

    int arow = tid >> 1, ahalf = tid & 1;   // loaders: 2 threads per row

    // ---- chunk loader (Kc = 64 fp16 = 128B/row) ----
    auto load_chunk = [&](int kc, int st) {
        uint32_t stg = sbase + OFF_STAGE + st * STAGE_SZ;
        // A: gathered child h rows, SW128 swizzle
        int child = (kc < 4) ? sa[arow] : sbb[arow];
        int col0 = (kc & 3) * 64 + ahalf * 32;
        const char* ah = (const char*)(g_Hh + (size_t)child * HDIM + col0);
        #pragma unroll
        for (int q = 0; q < 4; q++) {
            uint32_t boff = arow * 128 + ahalf * 64 + q * 16;
            cpa16(stg + ST_A + SWZ(boff), ah + q * 16);
        }
        // B: 128 gate rows (jj) x 128B data, padded stride 144B
        const char* wh = (const char*)(g_Wh + (size_t)(by * 128 + arow) * H2 + kc * 64 + ahalf * 32);
        #pragma unroll
        for (int q = 0; q < 4; q++) {
            uint32_t boff = arow * B_STRIDE + ahalf * 64 + q * 16;
            cpa16(stg + ST_B + boff, wh + q * 16);
        }
        cp_commit();
    };

    float acc[4][4][4];
    #pragma unroll
    for (int mt = 0; mt < 4; mt++)
        #pragma unroll
        for (int nb = 0; nb < 4; nb++)
            #pragma unroll
            for (int r = 0; r < 4; r++) acc[mt][nb][r] = 0.0f;

    load_chunk(0, 0);

    for (int kc = 0; kc < 8; kc++) {
        if (kc < 7) load_chunk(kc + 1, (kc + 1) & 1);
        if (kc < 7) cp_wait1(); else cp_wait0();
        __syncthreads();

        uint32_t stg = sbase + OFF_STAGE + (kc & 1) * STAGE_SZ;

        #pragma unroll
        for (int ks = 0; ks < 4; ks++) {
            int k0 = ks * 16;
            // B fragments via ldmatrix.x4: one x4 covers 2 nb (8 n-rows each, k0/k0+8)
            uint32_t bf[4][2];
            int sel = lane >> 3;         // matrix id 0..3
            int rinm = lane & 7;
            #pragma unroll
            for (int p = 0; p < 2; p++) {
                int n = wn * 32 + p * 16 + (sel >> 1) * 8 + rinm;
                uint32_t bptr = stg + ST_B + n * B_STRIDE + k0 * 2 + (sel & 1) * 16;
                ldmatrix4(bf[p * 2][0], bf[p * 2][1], bf[p * 2 + 1][0], bf[p * 2 + 1][1], bptr);
            }
            #pragma unroll
            for (int mt = 0; mt < 4; mt++) {
                int row = wm * 64 + mt * 16 + (lane & 15);
                uint32_t boff = SWZ((uint32_t)(row * 128 + k0 * 2 + (lane >> 4) * 16));
                uint32_t a0, a1, a2, a3;
                ldmatrix4(a0, a1, a2, a3, stg + ST_A + boff);
                #pragma unroll
                for (int nb = 0; nb < 4; nb++)
                    mma16816(acc[mt][nb][0], acc[mt][nb][1], acc[mt][nb][2], acc[mt][nb][3],
                             a0, a1, a2, a3, bf[nb][0], bf[nb][1]);
            }
        }
        __syncthreads();
    }

    // ---- stage gates to smem (reuse pipeline buffers): [128][GST] floats ----
    float* gates = (float*)(sp + OFF_STAGE);
    #pragma unroll
    for (int mt = 0; mt < 4; mt++) {
        #pragma unroll
        for (int nb = 0; nb < 4; nb++) {
            int r0 = wm * 64 + mt * 16 + (lane >> 2);
            int c0 = wn * 32 + nb * 8 + ((lane & 3) << 1);
            gates[r0 * GST + c0]           = acc[mt][nb][0];
            gates[r0 * GST + c0 + 1]       = acc[mt][nb][1];
            gates[(r0 + 8) * GST + c0]     = acc[mt][nb][2];
            gates[(r0 + 8) * GST + c0 + 1] = acc[mt][nb][3];
        }
    }
    __syncthreads();

    // ---- fused LSTM epilogue: 128 nodes x 32 hids (this by slice) ----
    int hl = tid & 31;                       // hid local 0..31
    int hid_g = by * 32 + hl;
    #pragma unroll 4
    for (int it = 0; it < 16; it++) {
        int m = (tid >> 5) + (it << 3);      // node local 0..127
        int node = base + m;
        int child = (by < 8) ? sa[m] : sbb[m];
        float4 gt = *(const float4*)(gates + m * GST + hl * 4);
        float4 xt = *(const float4*)(g_xtabp + (size_t)sty[m] * G4 + by * 128 + hl * 4);
        float ig = gt.x + xt.x;
        float fg = gt.y + xt.y;
        float gg = gt.z + xt.z;
        float og = gt.w + xt.w;
        float co = g_C[(size_t)child * HDIM + (hid_g & 255)];
        float cn = sigm(fg) * co + sigm(ig) * tanhf(gg);
        float hn = sigm(og) * tanhf(cn);
        out[(size_t)node * H2 + hid_g] = hn;
        if (by < 8) {
            g_C[(size_t)node * HDIM + hid_g] = cn;
            g_Hh[(size_t)node * HDIM + hid_g] = __float2half_rn(hn);
        }
    }
}

// ---------------- small levels (n <= 64): fp32 path ----------------
__global__ __launch_bounds__(256) void small_gates_kernel(
    const int* __restrict__ types, const int* __restrict__ a_idx,
    const int* __restrict__ b_idx, int s, int n) {
    __shared__ float hbuf[4][H2];
    __shared__ int stype[4], svalid[4], sa4[4], sb4[4];
    int t = threadIdx.x;
    int base = s + blockIdx.x * 4;
    if (t < 4) {
        int i = base + t;
        int v = (i < s + n);
        svalid[t] = v;
        sa4[t] = v ? a_idx[i] : N_NODES;
        sb4[t] = v ? b_idx[i] : N_NODES;
        stype[t] = v ? types[i] : 0;
    }
    __syncthreads();
    #pragma unroll
    for (int it = 0; it < 8; it++) {
        int idx = it * 256 + t;
        int r = idx >> 9;
        int k = idx & 511;
        int child = (k < HDIM) ? sa4[r] : sb4[r];
        int kk = k & 255;
        hbuf[r][k] = __half2float(g_Hh[child * HDIM + kk]);
    }
    __syncthreads();
    int j = blockIdx.y * 256 + t;
    float acc[4];
    #pragma unroll
    for (int r = 0; r < 4; r++) acc[r] = g_xtab[stype[r] * G4 + j];
    #pragma unroll 4
    for (int k = 0; k < H2; k++) {
        float w = g_WhhT[k * G4 + j];
        #pragma unroll
        for (int r = 0; r < 4; r++) acc[r] = fmaf(w, hbuf[r][k], acc[r]);
    }
    #pragma unroll
    for (int r = 0; r < 4; r++)
        if (svalid[r]) g_gates[(blockIdx.x * 4 + r) * G4 + j] = acc[r];
}

__global__ __launch_bounds__(256) void small_epi_kernel(
    const int* __restrict__ a_idx, const int* __restrict__ b_idx,
    float* __restrict__ out, int s) {
    int i = s + blockIdx.x;
    int t = threadIdx.x;
    int a = a_idx[i], b = b_idx[i];
    const float* gr = g_gates + (size_t)blockIdx.x * G4;
    #pragma unroll
    for (int h = 0; h < 2; h++) {
        int hid = (h << 8) + t;
        float ig = gr[0 * 512 + hid];
        float fg = gr[1 * 512 + hid];
        float gg = gr[2 * 512 + hid];
        float og = gr[3 * 512 + hid];
        int child = h ? b : a;
        float c_old = g_C[child * HDIM + t];
        float c_new = sigm(fg) * c_old + sigm(ig) * tanhf(gg);
        float h_new = sigm(og) * tanhf(c_new);
        out[i * H2 + hid] = h_new;
        if (h == 0) {
            g_C[i * HDIM + t] = c_new;
            g_Hh[i * HDIM + t] = __float2half_rn(h_new);
        }
    }
}

extern "C" void kernel_launch(void* const* d_in, const int* in_sizes, int n_in,
                              void* d_out, int out_size) {
    const int* types  = (const int*)d_in[0];
    const int* a_idx  = (const int*)d_in[1];
    const int* b_idx  = (const int*)d_in[2];
    const float* emb  = (const float*)d_in[3];
    const float* W_ih = (const float*)d_in[4];
    const float* W_hh = (const float*)d_in[5];
    const float* b_ih = (const float*)d_in[6];
    const float* b_hh = (const float*)d_in[7];
    float* out = (float*)d_out;

    cudaFuncSetAttribute(tc_level_kernel, cudaFuncAttributeMaxDynamicSharedMemorySize, SMEM_DYN);

    xtab_kernel<<<VOCAB, 256>>>(emb, W_ih, b_ih, b_hh);
    transpose_kernel<<<dim3(G4 / 32, H2 / 32), dim3(32, 8)>>>(W_hh);
    wconv_kernel<<<G4, 256>>>(W_hh);

    for (int d = 14; d >= 7; d--) {
        int n = 1 << d;
        int s = n - 1;
        tc_level_kernel<<<dim3(n / 128, 16), 256, SMEM_DYN>>>(types, a_idx, b_idx, out, s);
    }
    for (int d = 6; d >= 0; d--) {
        int n = 1 << d;
        int s = n - 1;
        small_gates_kernel<<<dim3((n + 3) / 4, 8), 256>>>(types, a_idx, b_idx, s, n);
        small_epi_kernel<<<n, 256>>>(a_idx, b_idx, out, s);
    }
}

// round 6
// speedup vs baseline: 1.5139x; 1.3385x over previous
#include <cuda_runtime.h>
#include <cuda_fp16.h>
#include <math.h>
#include <stdint.h>

#define N_NODES 32767
#define HDIM 256
#define H2 512
#define G4 2048
#define VOCAB 32

// ---------------- device state / tables ----------------
__device__ float  g_C[(N_NODES + 1) * HDIM];    // c state (sentinel row stays 0)
__device__ __half g_Hh[(N_NODES + 1) * HDIM];   // h state fp16 (sentinel row stays 0)
__device__ float  g_xtab[VOCAB * G4];           // unpermuted (small fp32 path)
__device__ float  g_xtabp[VOCAB * G4];          // permuted jj = hid*4+g (tensor path)
__device__ float  g_WhhT[H2 * G4];              // fp32 [k][j] (small path)
__device__ __half g_Wh[G4 * H2];                // permuted rows [jj][k] fp16
__device__ float  g_gates[64 * G4];             // small-level gate scratch

// ---- fast transcendentals: single MUFU.TANH each ----
__device__ __forceinline__ float tanh_fast(float x) {
    float y;
    asm("tanh.approx.f32 %0, %1;" : "=f"(y) : "f"(x));
    return y;
}
__device__ __forceinline__ float sigm_fast(float x) {
    return fmaf(0.5f, tanh_fast(0.5f * x), 0.5f);
}

__device__ __forceinline__ uint32_t smem_u32(const void* p) {
    uint32_t a;
    asm("{ .reg .u64 t; cvta.to.shared.u64 t, %1; cvt.u32.u64 %0, t; }" : "=r"(a) : "l"(p));
    return a;
}
__device__ __forceinline__ void cpa16(uint32_t dst, const void* src) {
    asm volatile("cp.async.cg.shared.global [%0], [%1], 16;" :: "r"(dst), "l"(src));
}
__device__ __forceinline__ void cp_commit() { asm volatile("cp.async.commit_group;"); }
__device__ __forceinline__ void cp_wait1() { asm volatile("cp.async.wait_group 1;"); }
__device__ __forceinline__ void cp_wait0() { asm volatile("cp.async.wait_group 0;"); }

__device__ __forceinline__ void ldmatrix4(uint32_t& r0, uint32_t& r1, uint32_t& r2, uint32_t& r3,
                                          uint32_t addr) {
    asm volatile("ldmatrix.sync.aligned.m8n8.x4.shared.b16 {%0,%1,%2,%3}, [%4];"
                 : "=r"(r0), "=r"(r1), "=r"(r2), "=r"(r3) : "r"(addr));
}
__device__ __forceinline__ void mma16816(float& d0, float& d1, float& d2, float& d3,
                                         uint32_t a0, uint32_t a1, uint32_t a2, uint32_t a3,
                                         uint32_t b0, uint32_t b1) {
    asm volatile(
        "mma.sync.aligned.m16n8k16.row.col.f32.f16.f16.f32 "
        "{%0,%1,%2,%3}, {%4,%5,%6,%7}, {%8,%9}, {%0,%1,%2,%3};"
        : "+f"(d0), "+f"(d1), "+f"(d2), "+f"(d3)
        : "r"(a0), "r"(a1), "r"(a2), "r"(a3), "r"(b0), "r"(b1));
}

#define SWZ(x) ((x) ^ (((x) >> 3) & 0x70))

// ---------------- smem layout (dynamic) ----------------
#define OFF_META   0
#define OFF_STAGE  2048
#define A_BYTES    16384            // 128 rows x 128B (SW128), Kc=64 fp16
#define B_STRIDE   144              // 72 fp16 per row (64 data + 8 pad)
#define B_BYTES    (128 * B_STRIDE) // 18432
#define STAGE_SZ   (A_BYTES + B_BYTES)   // 34816
#define ST_A       0
#define ST_B       A_BYTES
#define SMEM_DYN   (OFF_STAGE + 2 * STAGE_SZ)    // 71680  -> 2 CTAs/SM
#define GST        132              // gate staging row stride (floats)

// ---------------- prep kernels ----------------
__global__ __launch_bounds__(256) void xtab_kernel(const float* __restrict__ emb,
                                                   const float* __restrict__ W_ih,
                                                   const float* __restrict__ b_ih,
                                                   const float* __restrict__ b_hh) {
    __shared__ float se[256];
    int v = blockIdx.x;
    int t = threadIdx.x;
    se[t] = emb[v * 256 + t];
    __syncthreads();
    #pragma unroll
    for (int m = 0; m < 8; m++) {
        int j = m * 256 + t;
        float acc = b_ih[j] + b_hh[j];
        const float4* wr = (const float4*)(W_ih + j * 256);
        #pragma unroll 8
        for (int k4 = 0; k4 < 64; k4++) {
            float4 w = wr[k4];
            acc += w.x * se[k4 * 4 + 0] + w.y * se[k4 * 4 + 1]
                 + w.z * se[k4 * 4 + 2] + w.w * se[k4 * 4 + 3];
        }
        g_xtab[v * G4 + j] = acc;
        g_xtabp[v * G4 + (j & 511) * 4 + (j >> 9)] = acc;
    }
}

__global__ void transpose_kernel(const float* __restrict__ W_hh) {
    __shared__ float tile[32][33];
    int j0 = blockIdx.x * 32;
    int k0 = blockIdx.y * 32;
    int tx = threadIdx.x, ty = threadIdx.y;
    #pragma unroll
    for (int r = 0; r < 32; r += 8)
        tile[ty + r][tx] = W_hh[(j0 + ty + r) * H2 + k0 + tx];
    __syncthreads();
    #pragma unroll
    for (int r = 0; r < 32; r += 8)
        g_WhhT[(k0 + ty + r) * G4 + j0 + tx] = tile[tx][ty + r];
}

__global__ __launch_bounds__(256) void wconv_kernel(const float* __restrict__ W_hh) {
    int jj = blockIdx.x;
    int g = jj & 3, hid = jj >> 2;
    const float* src = W_hh + (g * 512 + hid) * H2;
    int t = threadIdx.x;
    #pragma unroll
    for (int k = t; k < H2; k += 256)
        g_Wh[jj * H2 + k] = __float2half_rn(src[k]);
}

// ---------------- HMMA level kernel: M=128 nodes, N=128 gates (by slice), K=512 ----------------
__global__ __launch_bounds__(256) void tc_level_kernel(
    const int* __restrict__ types, const int* __restrict__ a_idx,
    const int* __restrict__ b_idx, float* __restrict__ out, int s) {
    extern __shared__ char sp[];
    uint32_t sbase = smem_u32(sp);
    int tid = threadIdx.x;
    int lane = tid & 31;
    int wid = tid >> 5;
    int wm = wid >> 2;            // 0..1  (M half, 64 rows)
    int wn = wid & 3;             // 0..3  (N quarter, 32 cols)
    int by = blockIdx.y;          // gate slice jj in [by*128, by*128+128)
    int base = s + blockIdx.x * 128;

    int* sa  = (int*)(sp + OFF_META);
    int* sbb = (int*)(sp + OFF_META + 512);
    int* sty = (int*)(sp + OFF_META + 1024);
    if (tid < 128) {
        int i = base + tid;
        sa[tid]  = a_idx[i];
        sbb[tid] = b_idx[i];
        sty[tid] = types[i];
    }
    __syncthreads();

    int arow = tid >> 1, ahalf = tid & 1;   // loaders: 2 threads per row

    auto load_chunk = [&](int kc, int st) {
        uint32_t stg = sbase + OFF_STAGE + st * STAGE_SZ;
        int child = (kc < 4) ? sa[arow] : sbb[arow];
        int col0 = (kc & 3) * 64 + ahalf * 32;
        const char* ah = (const char*)(g_Hh + (size_t)child * HDIM + col0);
        #pragma unroll
        for (int q = 0; q < 4; q++) {
            uint32_t boff = arow * 128 + ahalf * 64 + q * 16;
            cpa16(stg + ST_A + SWZ(boff), ah + q * 16);
        }
        const char* wh = (const char*)(g_Wh + (size_t)(by * 128 + arow) * H2 + kc * 64 + ahalf * 32);
        #pragma unroll
        for (int q = 0; q < 4; q++) {
            uint32_t boff = arow * B_STRIDE + ahalf * 64 + q * 16;
            cpa16(stg + ST_B + boff, wh + q * 16);
        }
        cp_commit();
    };

    float acc[4][4][4];
    #pragma unroll
    for (int mt = 0; mt < 4; mt++)
        #pragma unroll
        for (int nb = 0; nb < 4; nb++)
            #pragma unroll
            for (int r = 0; r < 4; r++) acc[mt][nb][r] = 0.0f;

    load_chunk(0, 0);

    for (int kc = 0; kc < 8; kc++) {
        if (kc < 7) load_chunk(kc + 1, (kc + 1) & 1);
        if (kc < 7) cp_wait1(); else cp_wait0();
        __syncthreads();

        uint32_t stg = sbase + OFF_STAGE + (kc & 1) * STAGE_SZ;

        #pragma unroll
        for (int ks = 0; ks < 4; ks++) {
            int k0 = ks * 16;
            uint32_t bf[4][2];
            int sel = lane >> 3;
            int rinm = lane & 7;
            #pragma unroll
            for (int p = 0; p < 2; p++) {
                int n = wn * 32 + p * 16 + (sel >> 1) * 8 + rinm;
                uint32_t bptr = stg + ST_B + n * B_STRIDE + k0 * 2 + (sel & 1) * 16;
                ldmatrix4(bf[p * 2][0], bf[p * 2][1], bf[p * 2 + 1][0], bf[p * 2 + 1][1], bptr);
            }
            #pragma unroll
            for (int mt = 0; mt < 4; mt++) {
                int row = wm * 64 + mt * 16 + (lane & 15);
                uint32_t boff = SWZ((uint32_t)(row * 128 + k0 * 2 + (lane >> 4) * 16));
                uint32_t a0, a1, a2, a3;
                ldmatrix4(a0, a1, a2, a3, stg + ST_A + boff);
                #pragma unroll
                for (int nb = 0; nb < 4; nb++)
                    mma16816(acc[mt][nb][0], acc[mt][nb][1], acc[mt][nb][2], acc[mt][nb][3],
                             a0, a1, a2, a3, bf[nb][0], bf[nb][1]);
            }
        }
        __syncthreads();
    }

    // ---- stage gates to smem (reuse pipeline buffers): [128][GST] floats ----
    float* gates = (float*)(sp + OFF_STAGE);
    #pragma unroll
    for (int mt = 0; mt < 4; mt++) {
        #pragma unroll
        for (int nb = 0; nb < 4; nb++) {
            int r0 = wm * 64 + mt * 16 + (lane >> 2);
            int c0 = wn * 32 + nb * 8 + ((lane & 3) << 1);
            gates[r0 * GST + c0]           = acc[mt][nb][0];
            gates[r0 * GST + c0 + 1]       = acc[mt][nb][1];
            gates[(r0 + 8) * GST + c0]     = acc[mt][nb][2];
            gates[(r0 + 8) * GST + c0 + 1] = acc[mt][nb][3];
        }
    }
    __syncthreads();

    // ---- fused LSTM epilogue (MUFU.TANH fast path) ----
    int hl = tid & 31;                       // hid local 0..31
    int hid_g = by * 32 + hl;
    #pragma unroll 4
    for (int it = 0; it < 16; it++) {
        int m = (tid >> 5) + (it << 3);      // node local 0..127
        int node = base + m;
        int child = (by < 8) ? sa[m] : sbb[m];
        float4 gt = *(const float4*)(gates + m * GST + hl * 4);
        float4 xt = *(const float4*)(g_xtabp + (size_t)sty[m] * G4 + by * 128 + hl * 4);
        float ig = gt.x + xt.x;
        float fg = gt.y + xt.y;
        float gg = gt.z + xt.z;
        float og = gt.w + xt.w;
        float co = g_C[(size_t)child * HDIM + (hid_g & 255)];
        float cn = sigm_fast(fg) * co + sigm_fast(ig) * tanh_fast(gg);
        float hn = sigm_fast(og) * tanh_fast(cn);
        out[(size_t)node * H2 + hid_g] = hn;
        if (by < 8) {
            g_C[(size_t)node * HDIM + hid_g] = cn;
            g_Hh[(size_t)node * HDIM + hid_g] = __float2half_rn(hn);
        }
    }
}

// ---------------- small levels (n <= 64): fp32 path ----------------
__global__ __launch_bounds__(256) void small_gates_kernel(
    const int* __restrict__ types, const int* __restrict__ a_idx,
    const int* __restrict__ b_idx, int s, int n) {
    __shared__ float hbuf[4][H2];
    __shared__ int stype[4], svalid[4], sa4[4], sb4[4];
    int t = threadIdx.x;
    int base = s + blockIdx.x * 4;
    if (t < 4) {
        int i = base + t;
        int v = (i < s + n);
        svalid[t] = v;
        sa4[t] = v ? a_idx[i] : N_NODES;
        sb4[t] = v ? b_idx[i] : N_NODES;
        stype[t] = v ? types[i] : 0;
    }
    __syncthreads();
    #pragma unroll
    for (int it = 0; it < 8; it++) {
        int idx = it * 256 + t;
        int r = idx >> 9;
        int k = idx & 511;
        int child = (k < HDIM) ? sa4[r] : sb4[r];
        int kk = k & 255;
        hbuf[r][k] = __half2float(g_Hh[child * HDIM + kk]);
    }
    __syncthreads();
    int j = blockIdx.y * 256 + t;
    float acc[4];
    #pragma unroll
    for (int r = 0; r < 4; r++) acc[r] = g_xtab[stype[r] * G4 + j];
    #pragma unroll 4
    for (int k = 0; k < H2; k++) {
        float w = g_WhhT[k * G4 + j];
        #pragma unroll
        for (int r = 0; r < 4; r++) acc[r] = fmaf(w, hbuf[r][k], acc[r]);
    }
    #pragma unroll
    for (int r = 0; r < 4; r++)
        if (svalid[r]) g_gates[(blockIdx.x * 4 + r) * G4 + j] = acc[r];
}

__global__ __launch_bounds__(256) void small_epi_kernel(
    const int* __restrict__ a_idx, const int* __restrict__ b_idx,
    float* __restrict__ out, int s) {
    int i = s + blockIdx.x;
    int t = threadIdx.x;
    int a = a_idx[i], b = b_idx[i];
    const float* gr = g_gates + (size_t)blockIdx.x * G4;
    #pragma unroll
    for (int h = 0; h < 2; h++) {
        int hid = (h << 8) + t;
        float ig = gr[0 * 512 + hid];
        float fg = gr[1 * 512 + hid];
        float gg = gr[2 * 512 + hid];
        float og = gr[3 * 512 + hid];
        int child = h ? b : a;
        float c_old = g_C[child * HDIM + t];
        float c_new = sigm_fast(fg) * c_old + sigm_fast(ig) * tanh_fast(gg);
        float h_new = sigm_fast(og) * tanh_fast(c_new);
        out[i * H2 + hid] = h_new;
        if (h == 0) {
            g_C[i * HDIM + t] = c_new;
            g_Hh[i * HDIM + t] = __float2half_rn(h_new);
        }
    }
}

extern "C" void kernel_launch(void* const* d_in, const int* in_sizes, int n_in,
                              void* d_out, int out_size) {
    const int* types  = (const int*)d_in[0];
    const int* a_idx  = (const int*)d_in[1];
    const int* b_idx  = (const int*)d_in[2];
    const float* emb  = (const float*)d_in[3];
    const float* W_ih = (const float*)d_in[4];
    const float* W_hh = (const float*)d_in[5];
    const float* b_ih = (const float*)d_in[6];
    const float* b_hh = (const float*)d_in[7];
    float* out = (float*)d_out;

    cudaFuncSetAttribute(tc_level_kernel, cudaFuncAttributeMaxDynamicSharedMemorySize, SMEM_DYN);

    xtab_kernel<<<VOCAB, 256>>>(emb, W_ih, b_ih, b_hh);
    transpose_kernel<<<dim3(G4 / 32, H2 / 32), dim3(32, 8)>>>(W_hh);
    wconv_kernel<<<G4, 256>>>(W_hh);

    for (int d = 14; d >= 7; d--) {
        int n = 1 << d;
        int s = n - 1;
        tc_level_kernel<<<dim3(n / 128, 16), 256, SMEM_DYN>>>(types, a_idx, b_idx, out, s);
    }
    for (int d = 6; d >= 0; d--) {
        int n = 1 << d;
        int s = n - 1;
        small_gates_kernel<<<dim3((n + 3) / 4, 8), 256>>>(types, a_idx, b_idx, s, n);
        small_epi_kernel<<<n, 256>>>(a_idx, b_idx, out, s);
    }
}

// round 7
// speedup vs baseline: 4.2970x; 2.8384x over previous
#include <cuda_runtime.h>
#include <cuda_fp16.h>
#include <math.h>
#include <stdint.h>

#define N_NODES 32767
#define HDIM 256
#define H2 512
#define G4 2048
#define VOCAB 32
#define LEAF0 16383   // first leaf node; leaves are 16383..32766 (children >= N_NODES)

// ---------------- device state / tables ----------------
__device__ float  g_C[(N_NODES + 1) * HDIM];    // c state (sentinel row stays 0)
__device__ __half g_Hh[(N_NODES + 1) * HDIM];   // h state fp16 (sentinel row stays 0)
__device__ float  g_xtab[VOCAB * G4];           // unpermuted x_proj table
__device__ float  g_xtabp[VOCAB * G4];          // permuted jj = hid*4+g (tensor path)
__device__ float  g_WhhT[H2 * G4];              // fp32 [k][j] (small path)
__device__ __half g_Wh[G4 * H2];                // permuted rows [jj][k] fp16
__device__ float  g_gates[64 * G4];             // small-level gate scratch
// leaf tables (pure function of vocab type)
__device__ float  g_ltab_h[VOCAB * H2];         // full out row
__device__ float  g_ltab_c[VOCAB * HDIM];       // c state (first 256)
__device__ __half g_ltab_h16[VOCAB * HDIM];     // h state fp16 (first 256)

// ---- fast transcendentals: single MUFU.TANH each ----
__device__ __forceinline__ float tanh_fast(float x) {
    float y;
    asm("tanh.approx.f32 %0, %1;" : "=f"(y) : "f"(x));
    return y;
}
__device__ __forceinline__ float sigm_fast(float x) {
    return fmaf(0.5f, tanh_fast(0.5f * x), 0.5f);
}

__device__ __forceinline__ uint32_t smem_u32(const void* p) {
    uint32_t a;
    asm("{ .reg .u64 t; cvta.to.shared.u64 t, %1; cvt.u32.u64 %0, t; }" : "=r"(a) : "l"(p));
    return a;
}
__device__ __forceinline__ void cpa16(uint32_t dst, const void* src) {
    asm volatile("cp.async.cg.shared.global [%0], [%1], 16;" :: "r"(dst), "l"(src));
}
__device__ __forceinline__ void cp_commit() { asm volatile("cp.async.commit_group;"); }
__device__ __forceinline__ void cp_wait1() { asm volatile("cp.async.wait_group 1;"); }
__device__ __forceinline__ void cp_wait0() { asm volatile("cp.async.wait_group 0;"); }

__device__ __forceinline__ void ldmatrix4(uint32_t& r0, uint32_t& r1, uint32_t& r2, uint32_t& r3,
                                          uint32_t addr) {
    asm volatile("ldmatrix.sync.aligned.m8n8.x4.shared.b16 {%0,%1,%2,%3}, [%4];"
                 : "=r"(r0), "=r"(r1), "=r"(r2), "=r"(r3) : "r"(addr));
}
__device__ __forceinline__ void mma16816(float& d0, float& d1, float& d2, float& d3,
                                         uint32_t a0, uint32_t a1, uint32_t a2, uint32_t a3,
                                         uint32_t b0, uint32_t b1) {
    asm volatile(
        "mma.sync.aligned.m16n8k16.row.col.f32.f16.f16.f32 "
        "{%0,%1,%2,%3}, {%4,%5,%6,%7}, {%8,%9}, {%0,%1,%2,%3};"
        : "+f"(d0), "+f"(d1), "+f"(d2), "+f"(d3)
        : "r"(a0), "r"(a1), "r"(a2), "r"(a3), "r"(b0), "r"(b1));
}

#define SWZ(x) ((x) ^ (((x) >> 3) & 0x70))

// ---------------- smem layout (dynamic) ----------------
#define OFF_META   0
#define OFF_STAGE  2048
#define A_BYTES    16384
#define B_STRIDE   144
#define B_BYTES    (128 * B_STRIDE)
#define STAGE_SZ   (A_BYTES + B_BYTES)
#define ST_A       0
#define ST_B       A_BYTES
#define SMEM_DYN   (OFF_STAGE + 2 * STAGE_SZ)    // 71680 -> 2 CTAs/SM
#define GST        132

// ---------------- prep kernels ----------------
__global__ __launch_bounds__(256) void xtab_kernel(const float* __restrict__ emb,
                                                   const float* __restrict__ W_ih,
                                                   const float* __restrict__ b_ih,
                                                   const float* __restrict__ b_hh) {
    __shared__ float se[256];
    int v = blockIdx.x;
    int t = threadIdx.x;
    se[t] = emb[v * 256 + t];
    __syncthreads();
    #pragma unroll
    for (int m = 0; m < 8; m++) {
        int j = m * 256 + t;
        float acc = b_ih[j] + b_hh[j];
        const float4* wr = (const float4*)(W_ih + j * 256);
        #pragma unroll 8
        for (int k4 = 0; k4 < 64; k4++) {
            float4 w = wr[k4];
            acc += w.x * se[k4 * 4 + 0] + w.y * se[k4 * 4 + 1]
                 + w.z * se[k4 * 4 + 2] + w.w * se[k4 * 4 + 3];
        }
        g_xtab[v * G4 + j] = acc;
        g_xtabp[v * G4 + (j & 511) * 4 + (j >> 9)] = acc;
    }
}

// leaf tables: pure function of vocab type (h=0, c=0 children)
__global__ __launch_bounds__(256) void leaftab_kernel() {
    int v = blockIdx.x;
    int t = threadIdx.x;
    #pragma unroll
    for (int q = 0; q < 2; q++) {
        int hid = q * 256 + t;
        float ig = g_xtab[v * G4 + hid];
        float fg = g_xtab[v * G4 + 512 + hid];
        float gg = g_xtab[v * G4 + 1024 + hid];
        float og = g_xtab[v * G4 + 1536 + hid];
        (void)fg;
        float cn = sigm_fast(ig) * tanh_fast(gg);   // c_old = 0
        float hn = sigm_fast(og) * tanh_fast(cn);
        g_ltab_h[v * H2 + hid] = hn;
        if (q == 0) {
            g_ltab_c[v * HDIM + t] = cn;
            g_ltab_h16[v * HDIM + t] = __float2half_rn(hn);
        }
    }
}

// leaves: one warp per node, pure table copy
__global__ __launch_bounds__(256) void leaf_kernel(const int* __restrict__ types,
                                                   float* __restrict__ out) {
    int wid = threadIdx.x >> 5;
    int lane = threadIdx.x & 31;
    int node = LEAF0 + blockIdx.x * 8 + wid;
    if (node >= N_NODES) return;
    int v = types[node];
    const float4* sh = (const float4*)(g_ltab_h + (size_t)v * H2);
    float4* dh = (float4*)(out + (size_t)node * H2);
    #pragma unroll
    for (int q = 0; q < 4; q++) dh[lane + 32 * q] = sh[lane + 32 * q];
    const float4* sc = (const float4*)(g_ltab_c + (size_t)v * HDIM);
    float4* dc = (float4*)(g_C + (size_t)node * HDIM);
    #pragma unroll
    for (int q = 0; q < 2; q++) dc[lane + 32 * q] = sc[lane + 32 * q];
    const uint4* s16 = (const uint4*)(g_ltab_h16 + (size_t)v * HDIM);
    uint4* d16 = (uint4*)(g_Hh + (size_t)node * HDIM);
    d16[lane] = s16[lane];
}

__global__ void transpose_kernel(const float* __restrict__ W_hh) {
    __shared__ float tile[32][33];
    int j0 = blockIdx.x * 32;
    int k0 = blockIdx.y * 32;
    int tx = threadIdx.x, ty = threadIdx.y;
    #pragma unroll
    for (int r = 0; r < 32; r += 8)
        tile[ty + r][tx] = W_hh[(j0 + ty + r) * H2 + k0 + tx];
    __syncthreads();
    #pragma unroll
    for (int r = 0; r < 32; r += 8)
        g_WhhT[(k0 + ty + r) * G4 + j0 + tx] = tile[tx][ty + r];
}

__global__ __launch_bounds__(256) void wconv_kernel(const float* __restrict__ W_hh) {
    int jj = blockIdx.x;
    int g = jj & 3, hid = jj >> 2;
    const float* src = W_hh + (g * 512 + hid) * H2;
    int t = threadIdx.x;
    #pragma unroll
    for (int k = t; k < H2; k += 256)
        g_Wh[jj * H2 + k] = __float2half_rn(src[k]);
}

// ---------------- HMMA level kernel: M=128 nodes, N=128 gates (by slice), K=512 ----------------
__global__ __launch_bounds__(256) void tc_level_kernel(
    const int* __restrict__ types, const int* __restrict__ a_idx,
    const int* __restrict__ b_idx, float* __restrict__ out, int s) {
    extern __shared__ char sp[];
    uint32_t sbase = smem_u32(sp);
    int tid = threadIdx.x;
    int lane = tid & 31;
    int wid = tid >> 5;
    int wm = wid >> 2;
    int wn = wid & 3;
    int by = blockIdx.y;
    int base = s + blockIdx.x * 128;

    int* sa  = (int*)(sp + OFF_META);
    int* sbb = (int*)(sp + OFF_META + 512);
    int* sty = (int*)(sp + OFF_META + 1024);
    if (tid < 128) {
        int i = base + tid;
        sa[tid]  = a_idx[i];
        sbb[tid] = b_idx[i];
        sty[tid] = types[i];
    }
    __syncthreads();

    int arow = tid >> 1, ahalf = tid & 1;

    auto load_chunk = [&](int kc, int st) {
        uint32_t stg = sbase + OFF_STAGE + st * STAGE_SZ;
        int child = (kc < 4) ? sa[arow] : sbb[arow];
        int col0 = (kc & 3) * 64 + ahalf * 32;
        const char* ah = (const char*)(g_Hh + (size_t)child * HDIM + col0);
        #pragma unroll
        for (int q = 0; q < 4; q++) {
            uint32_t boff = arow * 128 + ahalf * 64 + q * 16;
            cpa16(stg + ST_A + SWZ(boff), ah + q * 16);
        }
        const char* wh = (const char*)(g_Wh + (size_t)(by * 128 + arow) * H2 + kc * 64 + ahalf * 32);
        #pragma unroll
        for (int q = 0; q < 4; q++) {
            uint32_t boff = arow * B_STRIDE + ahalf * 64 + q * 16;
            cpa16(stg + ST_B + boff, wh + q * 16);
        }
        cp_commit();
    };

    float acc[4][4][4];
    #pragma unroll
    for (int mt = 0; mt < 4; mt++)
        #pragma unroll
        for (int nb = 0; nb < 4; nb++)
            #pragma unroll
            for (int r = 0; r < 4; r++) acc[mt][nb][r] = 0.0f;

    load_chunk(0, 0);

    for (int kc = 0; kc < 8; kc++) {
        if (kc < 7) load_chunk(kc + 1, (kc + 1) & 1);
        if (kc < 7) cp_wait1(); else cp_wait0();
        __syncthreads();

        uint32_t stg = sbase + OFF_STAGE + (kc & 1) * STAGE_SZ;

        #pragma unroll
        for (int ks = 0; ks < 4; ks++) {
            int k0 = ks * 16;
            uint32_t bf[4][2];
            int sel = lane >> 3;
            int rinm = lane & 7;
            #pragma unroll
            for (int p = 0; p < 2; p++) {
                int n = wn * 32 + p * 16 + (sel >> 1) * 8 + rinm;
                uint32_t bptr = stg + ST_B + n * B_STRIDE + k0 * 2 + (sel & 1) * 16;
                ldmatrix4(bf[p * 2][0], bf[p * 2][1], bf[p * 2 + 1][0], bf[p * 2 + 1][1], bptr);
            }
            #pragma unroll
            for (int mt = 0; mt < 4; mt++) {
                int row = wm * 64 + mt * 16 + (lane & 15);
                uint32_t boff = SWZ((uint32_t)(row * 128 + k0 * 2 + (lane >> 4) * 16));
                uint32_t a0, a1, a2, a3;
                ldmatrix4(a0, a1, a2, a3, stg + ST_A + boff);
                #pragma unroll
                for (int nb = 0; nb < 4; nb++)
                    mma16816(acc[mt][nb][0], acc[mt][nb][1], acc[mt][nb][2], acc[mt][nb][3],
                             a0, a1, a2, a3, bf[nb][0], bf[nb][1]);
            }
        }
        __syncthreads();
    }

    // ---- stage gates to smem ----
    float* gates = (float*)(sp + OFF_STAGE);
    #pragma unroll
    for (int mt = 0; mt < 4; mt++) {
        #pragma unroll
        for (int nb = 0; nb < 4; nb++) {
            int r0 = wm * 64 + mt * 16 + (lane >> 2);
            int c0 = wn * 32 + nb * 8 + ((lane & 3) << 1);
            gates[r0 * GST + c0]           = acc[mt][nb][0];
            gates[r0 * GST + c0 + 1]       = acc[mt][nb][1];
            gates[(r0 + 8) * GST + c0]     = acc[mt][nb][2];
            gates[(r0 + 8) * GST + c0 + 1] = acc[mt][nb][3];
        }
    }
    __syncthreads();

    // ---- fused LSTM epilogue ----
    int hl = tid & 31;
    int hid_g = by * 32 + hl;
    #pragma unroll 4
    for (int it = 0; it < 16; it++) {
        int m = (tid >> 5) + (it << 3);
        int node = base + m;
        int child = (by < 8) ? sa[m] : sbb[m];
        float4 gt = *(const float4*)(gates + m * GST + hl * 4);
        float4 xt = *(const float4*)(g_xtabp + (size_t)sty[m] * G4 + by * 128 + hl * 4);
        float ig = gt.x + xt.x;
        float fg = gt.y + xt.y;
        float gg = gt.z + xt.z;
        float og = gt.w + xt.w;
        float co = g_C[(size_t)child * HDIM + (hid_g & 255)];
        float cn = sigm_fast(fg) * co + sigm_fast(ig) * tanh_fast(gg);
        float hn = sigm_fast(og) * tanh_fast(cn);
        out[(size_t)node * H2 + hid_g] = hn;
        if (by < 8) {
            g_C[(size_t)node * HDIM + hid_g] = cn;
            g_Hh[(size_t)node * HDIM + hid_g] = __float2half_rn(hn);
        }
    }
}

// ---------------- small levels (n <= 64): fp32 path ----------------
__global__ __launch_bounds__(256) void small_gates_kernel(
    const int* __restrict__ types, const int* __restrict__ a_idx,
    const int* __restrict__ b_idx, int s, int n) {
    __shared__ float hbuf[4][H2];
    __shared__ int stype[4], svalid[4], sa4[4], sb4[4];
    int t = threadIdx.x;
    int base = s + blockIdx.x * 4;
    if (t < 4) {
        int i = base + t;
        int v = (i < s + n);
        svalid[t] = v;
        sa4[t] = v ? a_idx[i] : N_NODES;
        sb4[t] = v ? b_idx[i] : N_NODES;
        stype[t] = v ? types[i] : 0;
    }
    __syncthreads();
    #pragma unroll
    for (int it = 0; it < 8; it++) {
        int idx = it * 256 + t;
        int r = idx >> 9;
        int k = idx & 511;
        int child = (k < HDIM) ? sa4[r] : sb4[r];
        int kk = k & 255;
        hbuf[r][k] = __half2float(g_Hh[child * HDIM + kk]);
    }
    __syncthreads();
    int j = blockIdx.y * 256 + t;
    float acc[4];
    #pragma unroll
    for (int r = 0; r < 4; r++) acc[r] = g_xtab[stype[r] * G4 + j];
    #pragma unroll 4
    for (int k = 0; k < H2; k++) {
        float w = g_WhhT[k * G4 + j];
        #pragma unroll
        for (int r = 0; r < 4; r++) acc[r] = fmaf(w, hbuf[r][k], acc[r]);
    }
    #pragma unroll
    for (int r = 0; r < 4; r++)
        if (svalid[r]) g_gates[(blockIdx.x * 4 + r) * G4 + j] = acc[r];
}

__global__ __launch_bounds__(256) void small_epi_kernel(
    const int* __restrict__ a_idx, const int* __restrict__ b_idx,
    float* __restrict__ out, int s) {
    int i = s + blockIdx.x;
    int t = threadIdx.x;
    int a = a_idx[i], b = b_idx[i];
    const float* gr = g_gates + (size_t)blockIdx.x * G4;
    #pragma unroll
    for (int h = 0; h < 2; h++) {
        int hid = (h << 8) + t;
        float ig = gr[0 * 512 + hid];
        float fg = gr[1 * 512 + hid];
        float gg = gr[2 * 512 + hid];
        float og = gr[3 * 512 + hid];
        int child = h ? b : a;
        float c_old = g_C[child * HDIM + t];
        float c_new = sigm_fast(fg) * c_old + sigm_fast(ig) * tanh_fast(gg);
        float h_new = sigm_fast(og) * tanh_fast(c_new);
        out[i * H2 + hid] = h_new;
        if (h == 0) {
            g_C[i * HDIM + t] = c_new;
            g_Hh[i * HDIM + t] = __float2half_rn(h_new);
        }
    }
}

extern "C" void kernel_launch(void* const* d_in, const int* in_sizes, int n_in,
                              void* d_out, int out_size) {
    const int* types  = (const int*)d_in[0];
    const int* a_idx  = (const int*)d_in[1];
    const int* b_idx  = (const int*)d_in[2];
    const float* emb  = (const float*)d_in[3];
    const float* W_ih = (const float*)d_in[4];
    const float* W_hh = (const float*)d_in[5];
    const float* b_ih = (const float*)d_in[6];
    const float* b_hh = (const float*)d_in[7];
    float* out = (float*)d_out;

    cudaFuncSetAttribute(tc_level_kernel, cudaFuncAttributeMaxDynamicSharedMemorySize, SMEM_DYN);

    xtab_kernel<<<VOCAB, 256>>>(emb, W_ih, b_ih, b_hh);
    transpose_kernel<<<dim3(G4 / 32, H2 / 32), dim3(32, 8)>>>(W_hh);
    wconv_kernel<<<G4, 256>>>(W_hh);
    leaftab_kernel<<<VOCAB, 256>>>();

    // level 14 (leaves): pure table lookup
    leaf_kernel<<<2048, 256>>>(types, out);

    // levels 13..7: tensor-core GEMM + fused epilogue
    for (int d = 13; d >= 7; d--) {
        int n = 1 << d;
        int s = n - 1;
        tc_level_kernel<<<dim3(n / 128, 16), 256, SMEM_DYN>>>(types, a_idx, b_idx, out, s);
    }
    // levels 6..0: fp32 path
    for (int d = 6; d >= 0; d--) {
        int n = 1 << d;
        int s = n - 1;
        small_gates_kernel<<<dim3((n + 3) / 4, 8), 256>>>(types, a_idx, b_idx, s, n);
        small_epi_kernel<<<n, 256>>>(a_idx, b_idx, out, s);
    }
}

// round 8
// speedup vs baseline: 4.4028x; 1.0246x over previous
#include <cuda_runtime.h>
#include <cuda_fp16.h>
#include <math.h>
#include <stdint.h>

#define N_NODES 32767
#define HDIM 256
#define H2 512
#define G4 2048
#define VOCAB 32
#define LEAF0 16383

// ---------------- device state / tables ----------------
__device__ float  g_C[(N_NODES + 1) * HDIM];
__device__ __half g_Hh[(N_NODES + 1) * HDIM];
__device__ float  g_xtab[VOCAB * G4];
__device__ float  g_xtabp[VOCAB * G4];
__device__ float  g_WhhT[H2 * G4];
__device__ __half g_Wh[G4 * H2];
__device__ float  g_gates[64 * G4];
__device__ float  g_ltab_h[VOCAB * H2];
__device__ float  g_ltab_c[VOCAB * HDIM];
__device__ __half g_ltab_h16[VOCAB * HDIM];

__device__ __forceinline__ float tanh_fast(float x) {
    float y;
    asm("tanh.approx.f32 %0, %1;" : "=f"(y) : "f"(x));
    return y;
}
__device__ __forceinline__ float sigm_fast(float x) {
    return fmaf(0.5f, tanh_fast(0.5f * x), 0.5f);
}

__device__ __forceinline__ uint32_t smem_u32(const void* p) {
    uint32_t a;
    asm("{ .reg .u64 t; cvta.to.shared.u64 t, %1; cvt.u32.u64 %0, t; }" : "=r"(a) : "l"(p));
    return a;
}
__device__ __forceinline__ void cpa16(uint32_t dst, const void* src) {
    asm volatile("cp.async.cg.shared.global [%0], [%1], 16;" :: "r"(dst), "l"(src));
}
__device__ __forceinline__ void cp_commit() { asm volatile("cp.async.commit_group;"); }
__device__ __forceinline__ void cp_wait1() { asm volatile("cp.async.wait_group 1;"); }
__device__ __forceinline__ void cp_wait0() { asm volatile("cp.async.wait_group 0;"); }

__device__ __forceinline__ void ldmatrix4(uint32_t& r0, uint32_t& r1, uint32_t& r2, uint32_t& r3,
                                          uint32_t addr) {
    asm volatile("ldmatrix.sync.aligned.m8n8.x4.shared.b16 {%0,%1,%2,%3}, [%4];"
                 : "=r"(r0), "=r"(r1), "=r"(r2), "=r"(r3) : "r"(addr));
}
__device__ __forceinline__ void mma16816(float& d0, float& d1, float& d2, float& d3,
                                         uint32_t a0, uint32_t a1, uint32_t a2, uint32_t a3,
                                         uint32_t b0, uint32_t b1) {
    asm volatile(
        "mma.sync.aligned.m16n8k16.row.col.f32.f16.f16.f32 "
        "{%0,%1,%2,%3}, {%4,%5,%6,%7}, {%8,%9}, {%0,%1,%2,%3};"
        : "+f"(d0), "+f"(d1), "+f"(d2), "+f"(d3)
        : "r"(a0), "r"(a1), "r"(a2), "r"(a3), "r"(b0), "r"(b1));
}

#define SWZ(x) ((x) ^ (((x) >> 3) & 0x70))

// ---------------- smem layout ----------------
#define OFF_META   0
#define OFF_STAGE  2048
#define A_BYTES    16384                 // 128 rows x 128B (SW128)
#define B_STRIDE   144                   // 72 fp16/row (64 + 8 pad)
#define B_BYTES    (64 * B_STRIDE)       // 9216
#define STAGE_SZ   (A_BYTES + B_BYTES)   // 25600
#define ST_A       0
#define ST_B       A_BYTES
#define SMEM_DYN   (OFF_STAGE + 2 * STAGE_SZ)   // 53248 -> 4 CTAs/SM
#define GST        68                    // gate staging row stride (floats)

// ---------------- prep: x table + leaf table in one kernel ----------------
__global__ __launch_bounds__(256) void xtab_kernel(const float* __restrict__ emb,
                                                   const float* __restrict__ W_ih,
                                                   const float* __restrict__ b_ih,
                                                   const float* __restrict__ b_hh) {
    __shared__ float se[256];
    __shared__ float sx[G4];
    int v = blockIdx.x;
    int t = threadIdx.x;
    se[t] = emb[v * 256 + t];
    __syncthreads();
    #pragma unroll
    for (int m = 0; m < 8; m++) {
        int j = m * 256 + t;
        float acc = b_ih[j] + b_hh[j];
        const float4* wr = (const float4*)(W_ih + j * 256);
        #pragma unroll 8
        for (int k4 = 0; k4 < 64; k4++) {
            float4 w = wr[k4];
            acc += w.x * se[k4 * 4 + 0] + w.y * se[k4 * 4 + 1]
                 + w.z * se[k4 * 4 + 2] + w.w * se[k4 * 4 + 3];
        }
        g_xtab[v * G4 + j] = acc;
        g_xtabp[v * G4 + (j & 511) * 4 + (j >> 9)] = acc;
        sx[j] = acc;
    }
    __syncthreads();
    // leaf table (children = zero state)
    #pragma unroll
    for (int q = 0; q < 2; q++) {
        int hid = q * 256 + t;
        float ig = sx[hid];
        float gg = sx[1024 + hid];
        float og = sx[1536 + hid];
        float cn = sigm_fast(ig) * tanh_fast(gg);
        float hn = sigm_fast(og) * tanh_fast(cn);
        g_ltab_h[v * H2 + hid] = hn;
        if (q == 0) {
            g_ltab_c[v * HDIM + t] = cn;
            g_ltab_h16[v * HDIM + t] = __float2half_rn(hn);
        }
    }
}

// ---------------- prep: transpose (fp32) + permuted fp16 convert, fused ----------------
__global__ void wprep_kernel(const float* __restrict__ W_hh) {
    __shared__ float tile[32][33];
    int j0 = blockIdx.x * 32;
    int k0 = blockIdx.y * 32;
    int tx = threadIdx.x, ty = threadIdx.y;
    #pragma unroll
    for (int r = 0; r < 32; r += 8) {
        int j = j0 + ty + r;
        float w = W_hh[j * H2 + k0 + tx];
        tile[ty + r][tx] = w;
        int jj = (j & 511) * 4 + (j >> 9);             // permuted row
        g_Wh[(size_t)jj * H2 + k0 + tx] = __float2half_rn(w);
    }
    __syncthreads();
    #pragma unroll
    for (int r = 0; r < 32; r += 8)
        g_WhhT[(k0 + ty + r) * G4 + j0 + tx] = tile[tx][ty + r];
}

// ---------------- leaves: table copy ----------------
__global__ __launch_bounds__(256) void leaf_kernel(const int* __restrict__ types,
                                                   float* __restrict__ out) {
    int wid = threadIdx.x >> 5;
    int lane = threadIdx.x & 31;
    int node = LEAF0 + blockIdx.x * 8 + wid;
    if (node >= N_NODES) return;
    int v = types[node];
    const float4* sh = (const float4*)(g_ltab_h + (size_t)v * H2);
    float4* dh = (float4*)(out + (size_t)node * H2);
    #pragma unroll
    for (int q = 0; q < 4; q++) dh[lane + 32 * q] = sh[lane + 32 * q];
    const float4* sc = (const float4*)(g_ltab_c + (size_t)v * HDIM);
    float4* dc = (float4*)(g_C + (size_t)node * HDIM);
    #pragma unroll
    for (int q = 0; q < 2; q++) dc[lane + 32 * q] = sc[lane + 32 * q];
    const uint4* s16 = (const uint4*)(g_ltab_h16 + (size_t)v * HDIM);
    uint4* d16 = (uint4*)(g_Hh + (size_t)node * HDIM);
    d16[lane] = s16[lane];
}

// ---------------- HMMA level kernel: M=128 nodes, N=64 gates (by slice), K=512 ----------------
__global__ __launch_bounds__(256, 4) void tc_level_kernel(
    const int* __restrict__ types, const int* __restrict__ a_idx,
    const int* __restrict__ b_idx, float* __restrict__ out, int s) {
    extern __shared__ char sp[];
    uint32_t sbase = smem_u32(sp);
    int tid = threadIdx.x;
    int lane = tid & 31;
    int wid = tid >> 5;
    int wm = wid >> 2;            // 0..1 (64 M-rows)
    int wn = wid & 3;             // 0..3 (16 N-cols)
    int by = blockIdx.y;          // gate slice jj in [by*64, by*64+64)
    int base = s + blockIdx.x * 128;

    int* sa  = (int*)(sp + OFF_META);
    int* sbb = (int*)(sp + OFF_META + 512);
    int* sty = (int*)(sp + OFF_META + 1024);
    if (tid < 128) {
        int i = base + tid;
        sa[tid]  = a_idx[i];
        sbb[tid] = b_idx[i];
        sty[tid] = types[i];
    }
    __syncthreads();

    int arow = tid >> 1, ahalf = tid & 1;     // A: 2 threads/row (128 rows)
    int brow = tid >> 2, bq = tid & 3;        // B: 4 threads/row (64 rows)

    auto load_chunk = [&](int kc, int st) {
        uint32_t stg = sbase + OFF_STAGE + st * STAGE_SZ;
        int child = (kc < 4) ? sa[arow] : sbb[arow];
        int col0 = (kc & 3) * 64 + ahalf * 32;
        const char* ah = (const char*)(g_Hh + (size_t)child * HDIM + col0);
        #pragma unroll
        for (int q = 0; q < 4; q++) {
            uint32_t boff = arow * 128 + ahalf * 64 + q * 16;
            cpa16(stg + ST_A + SWZ(boff), ah + q * 16);
        }
        const char* wh = (const char*)(g_Wh + (size_t)(by * 64 + brow) * H2 + kc * 64 + bq * 16);
        cpa16(stg + ST_B + brow * B_STRIDE + bq * 32, wh);
        cpa16(stg + ST_B + brow * B_STRIDE + bq * 32 + 16, wh + 64 * 2 * 16);   // second 16B: offset bq*16+? 
        cp_commit();
    };
    // NOTE on B addressing: each row is 64 fp16 = 128B; 4 threads per row, each
    // covering 32B. Fix the second cpa16 source to be contiguous +16B.
    auto load_chunk_fixed = [&](int kc, int st) {
        uint32_t stg = sbase + OFF_STAGE + st * STAGE_SZ;
        int child = (kc < 4) ? sa[arow] : sbb[arow];
        int col0 = (kc & 3) * 64 + ahalf * 32;
        const char* ah = (const char*)(g_Hh + (size_t)child * HDIM + col0);
        #pragma unroll
        for (int q = 0; q < 4; q++) {
            uint32_t boff = arow * 128 + ahalf * 64 + q * 16;
            cpa16(stg + ST_A + SWZ(boff), ah + q * 16);
        }
        const char* wh = (const char*)(g_Wh + (size_t)(by * 64 + brow) * H2 + kc * 64) + bq * 32;
        cpa16(stg + ST_B + brow * B_STRIDE + bq * 32, wh);
        cpa16(stg + ST_B + brow * B_STRIDE + bq * 32 + 16, wh + 16);
        cp_commit();
    };
    (void)load_chunk;

    float acc[4][2][4];
    #pragma unroll
    for (int mt = 0; mt < 4; mt++)
        #pragma unroll
        for (int nb = 0; nb < 2; nb++)
            #pragma unroll
            for (int r = 0; r < 4; r++) acc[mt][nb][r] = 0.0f;

    load_chunk_fixed(0, 0);

    for (int kc = 0; kc < 8; kc++) {
        if (kc < 7) load_chunk_fixed(kc + 1, (kc + 1) & 1);
        if (kc < 7) cp_wait1(); else cp_wait0();
        __syncthreads();

        uint32_t stg = sbase + OFF_STAGE + (kc & 1) * STAGE_SZ;

        #pragma unroll
        for (int ks = 0; ks < 4; ks++) {
            int k0 = ks * 16;
            uint32_t bf[2][2];
            int sel = lane >> 3;
            int rinm = lane & 7;
            {
                int n = wn * 16 + (sel >> 1) * 8 + rinm;
                uint32_t bptr = stg + ST_B + n * B_STRIDE + k0 * 2 + (sel & 1) * 16;
                ldmatrix4(bf[0][0], bf[0][1], bf[1][0], bf[1][1], bptr);
            }
            #pragma unroll
            for (int mt = 0; mt < 4; mt++) {
                int row = wm * 64 + mt * 16 + (lane & 15);
                uint32_t boff = SWZ((uint32_t)(row * 128 + k0 * 2 + (lane >> 4) * 16));
                uint32_t a0, a1, a2, a3;
                ldmatrix4(a0, a1, a2, a3, stg + ST_A + boff);
                #pragma unroll
                for (int nb = 0; nb < 2; nb++)
                    mma16816(acc[mt][nb][0], acc[mt][nb][1], acc[mt][nb][2], acc[mt][nb][3],
                             a0, a1, a2, a3, bf[nb][0], bf[nb][1]);
            }
        }
        __syncthreads();
    }

    // ---- stage gates to smem: [128][GST] floats ----
    float* gates = (float*)(sp + OFF_STAGE);
    #pragma unroll
    for (int mt = 0; mt < 4; mt++) {
        #pragma unroll
        for (int nb = 0; nb < 2; nb++) {
            int r0 = wm * 64 + mt * 16 + (lane >> 2);
            int c0 = wn * 16 + nb * 8 + ((lane & 3) << 1);
            gates[r0 * GST + c0]           = acc[mt][nb][0];
            gates[r0 * GST + c0 + 1]       = acc[mt][nb][1];
            gates[(r0 + 8) * GST + c0]     = acc[mt][nb][2];
            gates[(r0 + 8) * GST + c0 + 1] = acc[mt][nb][3];
        }
    }
    __syncthreads();

    // ---- fused LSTM epilogue: 128 nodes x 16 hids ----
    int hl = tid & 15;                         // hid local 0..15
    int hid_g = by * 16 + hl;                  // 0..511
    #pragma unroll 4
    for (int it = 0; it < 8; it++) {
        int m = (tid >> 4) + (it << 4);        // node local 0..127
        int node = base + m;
        int child = (by < 16) ? sa[m] : sbb[m];
        float4 gt = *(const float4*)(gates + m * GST + hl * 4);
        float4 xt = *(const float4*)(g_xtabp + (size_t)sty[m] * G4 + by * 64 + hl * 4);
        float ig = gt.x + xt.x;
        float fg = gt.y + xt.y;
        float gg = gt.z + xt.z;
        float og = gt.w + xt.w;
        float co = g_C[(size_t)child * HDIM + (hid_g & 255)];
        float cn = sigm_fast(fg) * co + sigm_fast(ig) * tanh_fast(gg);
        float hn = sigm_fast(og) * tanh_fast(cn);
        out[(size_t)node * H2 + hid_g] = hn;
        if (by < 16) {
            g_C[(size_t)node * HDIM + hid_g] = cn;
            g_Hh[(size_t)node * HDIM + hid_g] = __float2half_rn(hn);
        }
    }
}

// ---------------- small levels (n <= 64): fp32 path ----------------
__global__ __launch_bounds__(256) void small_gates_kernel(
    const int* __restrict__ types, const int* __restrict__ a_idx,
    const int* __restrict__ b_idx, int s, int n) {
    __shared__ float hbuf[4][H2];
    __shared__ int stype[4], svalid[4], sa4[4], sb4[4];
    int t = threadIdx.x;
    int base = s + blockIdx.x * 4;
    if (t < 4) {
        int i = base + t;
        int v = (i < s + n);
        svalid[t] = v;
        sa4[t] = v ? a_idx[i] : N_NODES;
        sb4[t] = v ? b_idx[i] : N_NODES;
        stype[t] = v ? types[i] : 0;
    }
    __syncthreads();
    #pragma unroll
    for (int it = 0; it < 8; it++) {
        int idx = it * 256 + t;
        int r = idx >> 9;
        int k = idx & 511;
        int child = (k < HDIM) ? sa4[r] : sb4[r];
        int kk = k & 255;
        hbuf[r][k] = __half2float(g_Hh[child * HDIM + kk]);
    }
    __syncthreads();
    int j = blockIdx.y * 256 + t;
    float acc[4];
    #pragma unroll
    for (int r = 0; r < 4; r++) acc[r] = g_xtab[stype[r] * G4 + j];
    #pragma unroll 4
    for (int k = 0; k < H2; k++) {
        float w = g_WhhT[k * G4 + j];
        #pragma unroll
        for (int r = 0; r < 4; r++) acc[r] = fmaf(w, hbuf[r][k], acc[r]);
    }
    #pragma unroll
    for (int r = 0; r < 4; r++)
        if (svalid[r]) g_gates[(blockIdx.x * 4 + r) * G4 + j] = acc[r];
}

__global__ __launch_bounds__(256) void small_epi_kernel(
    const int* __restrict__ a_idx, const int* __restrict__ b_idx,
    float* __restrict__ out, int s) {
    int i = s + blockIdx.x;
    int t = threadIdx.x;
    int a = a_idx[i], b = b_idx[i];
    const float* gr = g_gates + (size_t)blockIdx.x * G4;
    #pragma unroll
    for (int h = 0; h < 2; h++) {
        int hid = (h << 8) + t;
        float ig = gr[0 * 512 + hid];
        float fg = gr[1 * 512 + hid];
        float gg = gr[2 * 512 + hid];
        float og = gr[3 * 512 + hid];
        int child = h ? b : a;
        float c_old = g_C[child * HDIM + t];
        float c_new = sigm_fast(fg) * c_old + sigm_fast(ig) * tanh_fast(gg);
        float h_new = sigm_fast(og) * tanh_fast(c_new);
        out[i * H2 + hid] = h_new;
        if (h == 0) {
            g_C[i * HDIM + t] = c_new;
            g_Hh[i * HDIM + t] = __float2half_rn(h_new);
        }
    }
}

extern "C" void kernel_launch(void* const* d_in, const int* in_sizes, int n_in,
                              void* d_out, int out_size) {
    const int* types  = (const int*)d_in[0];
    const int* a_idx  = (const int*)d_in[1];
    const int* b_idx  = (const int*)d_in[2];
    const float* emb  = (const float*)d_in[3];
    const float* W_ih = (const float*)d_in[4];
    const float* W_hh = (const float*)d_in[5];
    const float* b_ih = (const float*)d_in[6];
    const float* b_hh = (const float*)d_in[7];
    float* out = (float*)d_out;

    cudaFuncSetAttribute(tc_level_kernel, cudaFuncAttributeMaxDynamicSharedMemorySize, SMEM_DYN);

    // launch #1..#3: prep + leaves; launch #4 = tc13 (profiled)
    xtab_kernel<<<VOCAB, 256>>>(emb, W_ih, b_ih, b_hh);
    wprep_kernel<<<dim3(G4 / 32, H2 / 32), dim3(32, 8)>>>(W_hh);
    leaf_kernel<<<2048, 256>>>(types, out);

    for (int d = 13; d >= 7; d--) {
        int n = 1 << d;
        int s = n - 1;
        tc_level_kernel<<<dim3(n / 128, 32), 256, SMEM_DYN>>>(types, a_idx, b_idx, out, s);
    }
    for (int d = 6; d >= 0; d--) {
        int n = 1 << d;
        int s = n - 1;
        small_gates_kernel<<<dim3((n + 3) / 4, 8), 256>>>(types, a_idx, b_idx, s, n);
        small_epi_kernel<<<n, 256>>>(a_idx, b_idx, out, s);
    }
}